// round 4
// baseline (speedup 1.0000x reference)
#include <cuda_runtime.h>
#include <math.h>

#define BN   8192
#define BT   64
#define NCTA 128
#define NTHR 256
#define TH   20
#define LP   30
#define DTC  0.1f
#define D2C  0.005f

struct SM {
    float4 Wp[3][64][32];      // [layer][k(0..31 x-part, 32..63 h-part)][d] = gates (i,f,g,o) at dim d
    float  H[3][32][BT];
    float  C[3][32][BT];
    float  xb[32][BT];
    float  XP[24][BT];         // [Xx(3), Xy(3), Px(9), Py(9)] per batch column
    float  Zs[2][TH][BT];
    float  pred[4][BT];
    float  WinT[24][32];
    float  bsum[3][128];
    float  Winb[32];
    float  WoutT[32][4];
    float  Woutb[4];
};

__device__ __forceinline__ float sigm(float z) {
    return __fdividef(1.0f, 1.0f + __expf(-z));
}
__device__ __forceinline__ float tanh_f(float z) {
    z = fminf(fmaxf(z, -15.0f), 15.0f);
    float e = __expf(-2.0f * z);
    return __fdividef(1.0f - e, 1.0f + e);
}

#define FMA4(ACC, W, XV)                          \
    ACC[0] = fmaf((W), (XV).x, ACC[0]);           \
    ACC[1] = fmaf((W), (XV).y, ACC[1]);           \
    ACC[2] = fmaf((W), (XV).z, ACC[2]);           \
    ACC[3] = fmaf((W), (XV).w, ACC[3]);

__device__ __forceinline__ void pack_weights(SM& s, int tid,
        const float* __restrict__ Wih, const float* __restrict__ Whh,
        const float* __restrict__ bih, const float* __restrict__ bhh) {
    for (int i = tid; i < 3 * 64 * 32; i += NTHR) {
        int d = i & 31, kk = (i >> 5) & 63, l = i >> 11;
        const float* W = (kk < 32) ? Wih : Whh;
        int k = kk & 31;
        int base = l * 4096 + d * 32 + k;
        float4 v;
        v.x = W[base];
        v.y = W[base + 1024];
        v.z = W[base + 2048];
        v.w = W[base + 3072];
        s.Wp[l][kk][d] = v;
    }
    for (int i = tid; i < 384; i += NTHR)
        ((float*)s.bsum)[i] = bih[i] + bhh[i];
}

// Kalman predict with Q[i][j] = g_i * g_j
__device__ __forceinline__ void kpred_f(float X[3], float P[9],
                                        float g0, float g1, float g2) {
    X[0] = X[0] + DTC * X[1] + D2C * X[2];
    X[1] = X[1] + DTC * X[2];
    float A[9];
#pragma unroll
    for (int j = 0; j < 3; j++) {
        A[0 * 3 + j] = P[0 * 3 + j] + DTC * P[1 * 3 + j] + D2C * P[2 * 3 + j];
        A[1 * 3 + j] = P[1 * 3 + j] + DTC * P[2 * 3 + j];
        A[2 * 3 + j] = P[2 * 3 + j];
    }
#pragma unroll
    for (int i = 0; i < 3; i++) {
        float qi = (i == 0) ? g0 : ((i == 1) ? g1 : g2);
        P[i * 3 + 0] = A[i * 3 + 0] + DTC * A[i * 3 + 1] + D2C * A[i * 3 + 2] + qi * g0;
        P[i * 3 + 1] = A[i * 3 + 1] + DTC * A[i * 3 + 2] + qi * g1;
        P[i * 3 + 2] = A[i * 3 + 2] + qi * g2;
    }
}

__device__ __forceinline__ void kupd_f(float X[3], float P[9], float z, float R) {
    float y = z - X[0];
    float S = P[0] + R;
    float inv = 1.0f / S;
    float K0 = P[0] * inv, K1 = P[3] * inv, K2 = P[6] * inv;
    X[0] += y * K0; X[1] += y * K1; X[2] += y * K2;
    float r0 = P[0], r1 = P[1], r2 = P[2];
    P[0] -= K0 * r0; P[1] -= K0 * r1; P[2] -= K0 * r2;
    P[3] -= K1 * r0; P[4] -= K1 * r1; P[5] -= K1 * r2;
    P[6] -= K2 * r0; P[7] -= K2 * r1; P[8] -= K2 * r2;
}

// input layer + 3 LSTM layers; leaves c[2] in s.xb. Ends with __syncthreads().
__device__ __forceinline__ void run_stack(SM& s, int bq, int dg) {
    // ---- input layer: x = tanh(XP @ Win^T + b) ----
    {
        float a0[4], a1[4];
        float bb0 = s.Winb[dg], bb1 = s.Winb[dg + 16];
#pragma unroll
        for (int b = 0; b < 4; b++) { a0[b] = bb0; a1[b] = bb1; }
#pragma unroll 4
        for (int k = 0; k < 24; k++) {
            float4 xv = *(const float4*)&s.XP[k][bq * 4];
            float w0 = s.WinT[k][dg];
            float w1 = s.WinT[k][dg + 16];
            FMA4(a0, w0, xv);
            FMA4(a1, w1, xv);
        }
        float4 r0, r1;
        r0.x = tanh_f(a0[0]); r0.y = tanh_f(a0[1]); r0.z = tanh_f(a0[2]); r0.w = tanh_f(a0[3]);
        r1.x = tanh_f(a1[0]); r1.y = tanh_f(a1[1]); r1.z = tanh_f(a1[2]); r1.w = tanh_f(a1[3]);
        *(float4*)&s.xb[dg][bq * 4]      = r0;
        *(float4*)&s.xb[dg + 16][bq * 4] = r1;
    }
    __syncthreads();

    // ---- 3 LSTM layers ----
#pragma unroll 1
    for (int l = 0; l < 3; l++) {
        float acc[2][4][4];
#pragma unroll
        for (int dp = 0; dp < 2; dp++)
#pragma unroll
            for (int q = 0; q < 4; q++) {
                float bb = s.bsum[l][q * 32 + dg + 16 * dp];
#pragma unroll
                for (int b = 0; b < 4; b++) acc[dp][q][b] = bb;
            }
        // x part
#pragma unroll 4
        for (int k = 0; k < 32; k++) {
            float4 xv = *(const float4*)&s.xb[k][bq * 4];
            float4 w0 = s.Wp[l][k][dg];
            float4 w1 = s.Wp[l][k][dg + 16];
            FMA4(acc[0][0], w0.x, xv); FMA4(acc[0][1], w0.y, xv);
            FMA4(acc[0][2], w0.z, xv); FMA4(acc[0][3], w0.w, xv);
            FMA4(acc[1][0], w1.x, xv); FMA4(acc[1][1], w1.y, xv);
            FMA4(acc[1][2], w1.z, xv); FMA4(acc[1][3], w1.w, xv);
        }
        // h part
#pragma unroll 4
        for (int k = 0; k < 32; k++) {
            float4 hv = *(const float4*)&s.H[l][k][bq * 4];
            float4 w0 = s.Wp[l][32 + k][dg];
            float4 w1 = s.Wp[l][32 + k][dg + 16];
            FMA4(acc[0][0], w0.x, hv); FMA4(acc[0][1], w0.y, hv);
            FMA4(acc[0][2], w0.z, hv); FMA4(acc[0][3], w0.w, hv);
            FMA4(acc[1][0], w1.x, hv); FMA4(acc[1][1], w1.y, hv);
            FMA4(acc[1][2], w1.z, hv); FMA4(acc[1][3], w1.w, hv);
        }
        __syncthreads();  // all reads of xb / H[l] complete before overwrite
#pragma unroll
        for (int dp = 0; dp < 2; dp++) {
            int d = dg + 16 * dp;
            float4 cold = *(const float4*)&s.C[l][d][bq * 4];
            float co[4] = {cold.x, cold.y, cold.z, cold.w};
            float cnv[4], hnv[4];
#pragma unroll
            for (int b = 0; b < 4; b++) {
                float ig = sigm(acc[dp][0][b]);
                float fg = sigm(acc[dp][1][b]);
                float gg = tanh_f(acc[dp][2][b]);
                float og = sigm(acc[dp][3][b]);
                float c  = fmaf(fg, co[b], ig * gg);
                float h  = og * tanh_f(c);
                cnv[b] = c; hnv[b] = h;
            }
            float4 cn, hn;
            cn.x = cnv[0]; cn.y = cnv[1]; cn.z = cnv[2]; cn.w = cnv[3];
            hn.x = hnv[0]; hn.y = hnv[1]; hn.z = hnv[2]; hn.w = hnv[3];
            *(float4*)&s.C[l][d][bq * 4]  = cn;
            *(float4*)&s.H[l][d][bq * 4]  = hn;
            *(float4*)&s.xb[d][bq * 4]    = cn;   // x for next layer = cell state
        }
        __syncthreads();
    }
}

__global__ void __launch_bounds__(NTHR, 1)
kalman_lstm_kernel(const float* __restrict__ hist,
                   const float* __restrict__ mx,  const float* __restrict__ my,
                   const float* __restrict__ vsx, const float* __restrict__ asx,
                   const float* __restrict__ Rxp, const float* __restrict__ Ryp,
                   const float* __restrict__ Gx,  const float* __restrict__ Gy,
                   const float* __restrict__ WinW, const float* __restrict__ Winb,
                   const float* __restrict__ eWih, const float* __restrict__ eWhh,
                   const float* __restrict__ ebih, const float* __restrict__ ebhh,
                   const float* __restrict__ dWih, const float* __restrict__ dWhh,
                   const float* __restrict__ dbih, const float* __restrict__ dbhh,
                   const float* __restrict__ WoutW, const float* __restrict__ Woutb,
                   float* __restrict__ out)
{
    extern __shared__ char smraw[];
    SM& s = *reinterpret_cast<SM*>(smraw);
    const int tid = threadIdx.x;
    const int b0  = blockIdx.x * BT;
    const int bq  = tid & 15;
    const int dg  = tid >> 4;

    // ---- one-time setup ----
    pack_weights(s, tid, eWih, eWhh, ebih, ebhh);
    for (int i = tid; i < 24 * 32; i += NTHR) {
        int d = i & 31, k = i >> 5;
        ((float*)s.WinT)[i] = WinW[d * 24 + k];
    }
    if (tid < 32) s.Winb[tid] = Winb[tid];
    if (tid < 128) { int k = tid >> 2, q = tid & 3; s.WoutT[k][q] = WoutW[q * 32 + k]; }
    if (tid < 4)  s.Woutb[tid] = Woutb[tid];
    for (int i = tid; i < BT * 40; i += NTHR) {
        int b = i / 40, j = i % 40;
        s.Zs[j & 1][j >> 1][b] = hist[(size_t)(b0 + b) * 40 + j];
    }
    for (int i = tid; i < 3 * 32 * BT; i += NTHR) {
        ((float*)s.H)[i] = 0.f;
        ((float*)s.C)[i] = 0.f;
    }

    const float rx = Rxp[0] * Rxp[0], ry = Ryp[0] * Ryp[0];
    const float vv = vsx[0] * vsx[0], aa = asx[0] * asx[0];
    const float gxe0 = Gx[0] * mx[0], gxe1 = Gx[1] * mx[0], gxe2 = Gx[2] * mx[0];
    const float gye0 = Gy[0] * my[0], gye1 = Gy[1] * my[0], gye2 = Gy[2] * my[0];
    const float gx0 = Gx[0], gx1 = Gx[1], gx2 = Gx[2];
    const float gy0 = Gy[0], gy1 = Gy[1], gy2 = Gy[2];

    if (tid < BT) {
        int b = tid;
#pragma unroll
        for (int j = 0; j < 24; j++) s.XP[j][b] = 0.f;
        s.XP[0][b]  = hist[(size_t)(b0 + b) * 40 + 0];
        s.XP[3][b]  = hist[(size_t)(b0 + b) * 40 + 1];
        s.XP[6][b]  = rx; s.XP[10][b] = vv; s.XP[14][b] = aa;   // Px diag
        s.XP[15][b] = rx; s.XP[19][b] = vv; s.XP[23][b] = aa;   // Py diag (ref uses R_x too)
    }
    __syncthreads();

    // ---- encoder: t = 1..19 ----
    for (int t = 1; t < TH; t++) {
        run_stack(s, bq, dg);
        if (tid < 128) {
            int b = tid & 63, f = tid >> 6;
            int xo = f ? 3 : 0, po = f ? 15 : 6;
            float X[3], P[9];
#pragma unroll
            for (int i = 0; i < 3; i++) X[i] = s.XP[xo + i][b];
#pragma unroll
            for (int i = 0; i < 9; i++) P[i] = s.XP[po + i][b];
            if (f == 0) kpred_f(X, P, gxe0, gxe1, gxe2);
            else        kpred_f(X, P, gye0, gye1, gye2);
            kupd_f(X, P, s.Zs[f][t][b], f ? ry : rx);
#pragma unroll
            for (int i = 0; i < 3; i++) s.XP[xo + i][b] = X[i];
#pragma unroll
            for (int i = 0; i < 9; i++) s.XP[po + i][b] = P[i];
        }
        __syncthreads();
    }

    // ---- swap in decoder weights ----
    pack_weights(s, tid, dWih, dWhh, dbih, dbhh);
    __syncthreads();

    // ---- decoder: 30 steps ----
    for (int st = 0; st < LP; st++) {
        run_stack(s, bq, dg);
        // pred = c[2] @ Wout^T + b : 256 threads, one (q,b) dot each
        {
            int q = tid >> 6, b = tid & 63;
            float a = s.Woutb[q];
#pragma unroll 8
            for (int k = 0; k < 32; k++) a = fmaf(s.xb[k][b], s.WoutT[k][q], a);
            s.pred[q][b] = a;
        }
        __syncthreads();
        if (tid < 128) {
            int b = tid & 63, f = tid >> 6;
            int xo = f ? 3 : 0, po = f ? 15 : 6;
            float X[3], P[9];
#pragma unroll
            for (int i = 0; i < 3; i++) X[i] = s.XP[xo + i][b];
#pragma unroll
            for (int i = 0; i < 9; i++) P[i] = s.XP[po + i][b];
            X[2] = DTC * s.pred[f][b];
            float sc = s.pred[2 + f][b];
            float q0 = sc * (f ? gy0 : gx0);
            float q1 = sc * (f ? gy1 : gx1);
            float q2 = sc * (f ? gy2 : gx2);
            kpred_f(X, P, q0, q1, q2);
#pragma unroll
            for (int i = 0; i < 3; i++) s.XP[xo + i][b] = X[i];
#pragma unroll
            for (int i = 0; i < 9; i++) s.XP[po + i][b] = P[i];
            float* o = out + (size_t)(b0 + b) * (LP * 5) + st * 5;
            if (f == 0) { o[0] = X[0]; o[2] = sqrtf(P[0]); }
            else        { o[1] = X[0]; o[3] = sqrtf(P[0]); o[4] = 0.0f; }
        }
        __syncthreads();
    }
}

extern "C" void kernel_launch(void* const* d_in, const int* in_sizes, int n_in,
                              void* d_out, int out_size) {
    cudaFuncSetAttribute(kalman_lstm_kernel,
                         cudaFuncAttributeMaxDynamicSharedMemorySize,
                         (int)sizeof(SM));
    kalman_lstm_kernel<<<NCTA, NTHR, sizeof(SM)>>>(
        (const float*)d_in[0],  (const float*)d_in[1],  (const float*)d_in[2],
        (const float*)d_in[3],  (const float*)d_in[4],  (const float*)d_in[5],
        (const float*)d_in[6],  (const float*)d_in[7],  (const float*)d_in[8],
        (const float*)d_in[9],  (const float*)d_in[10], (const float*)d_in[11],
        (const float*)d_in[12], (const float*)d_in[13], (const float*)d_in[14],
        (const float*)d_in[15], (const float*)d_in[16], (const float*)d_in[17],
        (const float*)d_in[18], (const float*)d_in[19], (const float*)d_in[20],
        (float*)d_out);
}